// round 12
// baseline (speedup 1.0000x reference)
#include <cuda_runtime.h>
#include <cstddef>

#define B_   32
#define T_   2048
#define E_   128
#define G_   8              // CTAs per batch
#define ROWS 256            // T_ / G_  rows per CTA
#define NW   16             // warps per CTA
#define RPW  16             // rows per warp
#define NCTA (B_ * G_)      // 256 CTAs; 2 per SM co-resident (296 slots)
#define THREADS 512
#define INV_T (1.0f / 2048.0f)

// ---------------- scratch (device globals; zero-init; no allocation) -------
__device__ float  g_s_part[2][B_][G_][E_];
__device__ float  g_c_part[2][B_][G_][E_];
__device__ float2 g_stats [2][B_][G_];     // per-CTA (max, sumexp)
__device__ float  g_o_part[2][B_][G_][E_];
__device__ unsigned g_bar[B_][4];          // per-batch phase counters
__device__ unsigned g_tick;                // reset ticket

static __device__ __forceinline__ float dot4(float4 a, float4 b) {
    return fmaf(a.x, b.x, fmaf(a.y, b.y, fmaf(a.z, b.z, a.w * b.w)));
}
static __device__ __forceinline__ float wsum(float v) {
    #pragma unroll
    for (int off = 16; off; off >>= 1) v += __shfl_xor_sync(0xffffffffu, v, off);
    return v;
}
static __device__ __forceinline__ float wmax(float v) {
    #pragma unroll
    for (int off = 16; off; off >>= 1) v = fmaxf(v, __shfl_xor_sync(0xffffffffu, v, off));
    return v;
}

// per-batch spin barrier; all 256 CTAs co-resident (2/SM), so spinning is safe
static __device__ __forceinline__ void batch_bar(unsigned* cnt) {
    __threadfence();
    __syncthreads();
    if (threadIdx.x == 0) {
        atomicAdd(cnt, 1u);
        while (*(volatile unsigned*)cnt < G_) __nanosleep(32);
        __threadfence();
    }
    __syncthreads();
}

// ===========================================================================
__global__ void __launch_bounds__(THREADS, 2) fused_attn(
    const float* __restrict__ x1, const float* __restrict__ x2,
    const float* __restrict__ W1, const float* __restrict__ bb1,
    const float* __restrict__ U1, const float* __restrict__ W2,
    const float* __restrict__ bb2, const float* __restrict__ U2,
    float* __restrict__ out)
{
    const int b    = blockIdx.x >> 3;
    const int g    = blockIdx.x & 7;
    const int tid  = threadIdx.x;
    const int lane = tid & 31;
    const int w    = tid >> 5;
    const int t0   = g * ROWS;
    const int rbase = w * RPW;

    __shared__ float4 sred[2 * NW][32];  // 16 KB warp-reduction scratch
    __shared__ float  vsh[2][E_];        // s (phase B) then c (phase C)
    __shared__ float  tsh[2][ROWS];      // d -> et -> softmax weights
    __shared__ float2 stsh[2][8];        // per-warp stats (8 warps/tensor)
    __shared__ float  s_m[2], s_iz[2];

    const float4* p1 = (const float4*)(x1 + ((size_t)b * T_ + t0) * E_);
    const float4* p2 = (const float4*)(x2 + ((size_t)b * T_ + t0) * E_);

    // ================= Phase A: column sums + row dots d ===================
    {
        float4 w1l = ((const float4*)W1)[lane];
        float4 w2l = ((const float4*)W2)[lane];
        float4 s1a = {0,0,0,0}, s2a = {0,0,0,0};
        #pragma unroll 2
        for (int rr = 0; rr < RPW; rr++) {
            int row = rbase + rr;
            float4 v1 = __ldg(p1 + row * 32 + lane);
            float4 v2 = __ldg(p2 + row * 32 + lane);
            s1a.x += v1.x; s1a.y += v1.y; s1a.z += v1.z; s1a.w += v1.w;
            s2a.x += v2.x; s2a.y += v2.y; s2a.z += v2.z; s2a.w += v2.w;
            float d1 = wsum(dot4(v1, w1l));
            float d2 = wsum(dot4(v2, w2l));
            if (lane == 0) { tsh[0][row] = d1; tsh[1][row] = d2; }
        }
        sred[w][lane] = s1a;
        sred[NW + w][lane] = s2a;
        __syncthreads();
        if (tid < 64) {
            int ti = tid >> 5;
            float4 s = sred[ti * NW][lane];
            #pragma unroll
            for (int k = 1; k < NW; k++) {
                float4 v = sred[ti * NW + k][lane];
                s.x += v.x; s.y += v.y; s.z += v.z; s.w += v.w;
            }
            ((float4*)&g_s_part[ti][b][g][0])[lane] = s;
        }
    }
    batch_bar(&g_bar[b][0]);

    if (tid < 256) {
        int ti = tid >> 7, e = tid & 127;
        float acc = 0.f;
        #pragma unroll
        for (int gg = 0; gg < G_; gg++) acc += g_s_part[ti][b][gg][e];
        vsh[ti][e] = acc;
    }
    __syncthreads();

    // ================= Phase B: c partials (x rows L2-hot) =================
    {
        float4 s1l = ((const float4*)vsh[0])[lane];
        float4 s2l = ((const float4*)vsh[1])[lane];
        float4 c1a = {0,0,0,0}, c2a = {0,0,0,0};
        #pragma unroll 2
        for (int rr = 0; rr < RPW; rr++) {
            int row = rbase + rr;
            float4 v1 = __ldg(p1 + row * 32 + lane);
            float4 v2 = __ldg(p2 + row * 32 + lane);
            float a1 = wsum(dot4(v1, s2l));   // x1 . s2
            float a2 = wsum(dot4(v2, s1l));   // x2 . s1
            c1a.x = fmaf(a1, v2.x, c1a.x); c1a.y = fmaf(a1, v2.y, c1a.y);
            c1a.z = fmaf(a1, v2.z, c1a.z); c1a.w = fmaf(a1, v2.w, c1a.w);
            c2a.x = fmaf(a2, v1.x, c2a.x); c2a.y = fmaf(a2, v1.y, c2a.y);
            c2a.z = fmaf(a2, v1.z, c2a.z); c2a.w = fmaf(a2, v1.w, c2a.w);
        }
        sred[w][lane] = c1a;
        sred[NW + w][lane] = c2a;
        __syncthreads();
        if (tid < 64) {
            int ti = tid >> 5;
            float4 s = sred[ti * NW][lane];
            #pragma unroll
            for (int k = 1; k < NW; k++) {
                float4 v = sred[ti * NW + k][lane];
                s.x += v.x; s.y += v.y; s.z += v.z; s.w += v.w;
            }
            ((float4*)&g_c_part[ti][b][g][0])[lane] = s;
        }
    }
    batch_bar(&g_bar[b][1]);

    if (tid < 256) {
        int ti = tid >> 7, e = tid & 127;
        float acc = 0.f;
        #pragma unroll
        for (int gg = 0; gg < G_; gg++) acc += g_c_part[ti][b][gg][e];
        vsh[ti][e] = acc * INV_T;
    }
    __syncthreads();

    // ================= Phase C: logits + per-CTA softmax stats =============
    {
        int p    = tid >> 8;          // tensor
        int tloc = tid & 255;         // one thread per t (2x256 = 512)
        int wp   = tloc >> 5;         // warp within tensor (0..7)
        int t    = t0 + tloc;
        const float* U    = p ? U2  : U1;
        const float* bias = p ? bb2 : bb1;
        float acc = 0.f;
        #pragma unroll 8
        for (int e = 0; e < E_; e++)
            acc = fmaf(vsh[p][e], __ldg(&U[e * T_ + t]), acc);
        float et = acc + tsh[p][tloc] + __ldg(&bias[t]);
        tsh[p][tloc] = et;            // each thread owns (p,tloc): no race
        float m = wmax(et);
        float z = wsum(__expf(et - m));
        if (lane == 0) stsh[p][wp] = make_float2(m, z);
    }
    __syncthreads();
    if (tid < 2) {
        float m = -3.4e38f;
        #pragma unroll
        for (int i = 0; i < 8; i++) m = fmaxf(m, stsh[tid][i].x);
        float z = 0.f;
        #pragma unroll
        for (int i = 0; i < 8; i++) {
            float2 st = stsh[tid][i];
            z += st.y * __expf(st.x - m);
        }
        g_stats[tid][b][g] = make_float2(m, z);
    }
    batch_bar(&g_bar[b][2]);
    if (tid < 2) {
        float m = -3.4e38f;
        #pragma unroll
        for (int gg = 0; gg < G_; gg++) m = fmaxf(m, g_stats[tid][b][gg].x);
        float z = 0.f;
        #pragma unroll
        for (int gg = 0; gg < G_; gg++) {
            float2 st = g_stats[tid][b][gg];
            z += st.y * __expf(st.x - m);
        }
        s_m[tid]  = m;
        s_iz[tid] = 1.0f / z;
    }
    __syncthreads();

    // ================= Phase D: softmax weights + weighted sums ============
    {
        int p = tid >> 8, rr = tid & 255;
        tsh[p][rr] = __expf(tsh[p][rr] - s_m[p]) * s_iz[p];
    }
    __syncthreads();
    {
        float4 o1a = {0,0,0,0}, o2a = {0,0,0,0};
        #pragma unroll 2
        for (int rr = 0; rr < RPW; rr++) {
            int row = rbase + rr;
            float wt1 = tsh[0][row];
            float wt2 = tsh[1][row];
            float4 v1 = __ldg(p1 + row * 32 + lane);
            float4 v2 = __ldg(p2 + row * 32 + lane);
            o1a.x = fmaf(wt1, v1.x, o1a.x); o1a.y = fmaf(wt1, v1.y, o1a.y);
            o1a.z = fmaf(wt1, v1.z, o1a.z); o1a.w = fmaf(wt1, v1.w, o1a.w);
            o2a.x = fmaf(wt2, v2.x, o2a.x); o2a.y = fmaf(wt2, v2.y, o2a.y);
            o2a.z = fmaf(wt2, v2.z, o2a.z); o2a.w = fmaf(wt2, v2.w, o2a.w);
        }
        sred[w][lane] = o1a;
        sred[NW + w][lane] = o2a;
        __syncthreads();
        if (tid < 64) {
            int ti = tid >> 5;
            float4 s = sred[ti * NW][lane];
            #pragma unroll
            for (int k = 1; k < NW; k++) {
                float4 v = sred[ti * NW + k][lane];
                s.x += v.x; s.y += v.y; s.z += v.z; s.w += v.w;
            }
            ((float4*)&g_o_part[ti][b][g][0])[lane] = s;
        }
    }
    batch_bar(&g_bar[b][3]);

    // ---------------- output: CTA g writes its 32 of 256 values ------------
    if (tid < 32) {
        int idx = g * 32 + tid;
        int ti = idx >> 7, e = idx & 127;
        float acc = 0.f;
        #pragma unroll
        for (int gg = 0; gg < G_; gg++) acc += g_o_part[ti][b][gg][e];
        out[b * 256 + idx] = acc;
    }

    // ---------------- cleanup: last CTA resets all counters ----------------
    __syncthreads();
    if (tid == 0) {
        unsigned old = atomicAdd(&g_tick, 1u);
        if (old == NCTA - 1) {
            #pragma unroll
            for (int i = 0; i < B_; i++) {
                g_bar[i][0] = 0u; g_bar[i][1] = 0u;
                g_bar[i][2] = 0u; g_bar[i][3] = 0u;
            }
            g_tick = 0u;
        }
    }
}

// ===========================================================================
extern "C" void kernel_launch(void* const* d_in, const int* in_sizes, int n_in,
                              void* d_out, int out_size)
{
    const float* x1 = (const float*)d_in[0];
    const float* x2 = (const float*)d_in[1];
    const float* W1 = (const float*)d_in[2];
    const float* b1 = (const float*)d_in[3];
    const float* U1 = (const float*)d_in[4];
    const float* W2 = (const float*)d_in[5];
    const float* b2 = (const float*)d_in[6];
    const float* U2 = (const float*)d_in[7];
    float* out = (float*)d_out;

    fused_attn<<<NCTA, THREADS>>>(x1, x2, W1, b1, U1, W2, b2, U2, out);
}

// round 13
// speedup vs baseline: 1.4071x; 1.4071x over previous
#include <cuda_runtime.h>
#include <cstddef>

#define B_   32
#define T_   2048
#define E_   128
#define G_   4              // CTAs per batch
#define ROWS 512            // T_ / G_  rows per CTA
#define NW   32             // warps per CTA
#define RPW  16             // rows per warp
#define INV_T (1.0f / 2048.0f)

// ---------------- scratch (device globals; zero-init; no allocation) -------
__device__ float  g_s_part[2][B_][G_][E_];   // per-CTA column-sum partials
__device__ float  g_c_part[2][B_][G_][E_];   // per-CTA c partials
__device__ float2 g_stats [2][B_][G_];       // per-CTA (max, sumexp) stats
__device__ float  g_o_part[2][B_][G_][E_];   // per-CTA weighted-sum partials
__device__ unsigned g_bar[B_][5];            // per-batch phase counters (self-reset)

static __device__ __forceinline__ float dot4(float4 a, float4 b) {
    return fmaf(a.x, b.x, fmaf(a.y, b.y, fmaf(a.z, b.z, a.w * b.w)));
}
static __device__ __forceinline__ float wsum(float v) {
    #pragma unroll
    for (int off = 16; off; off >>= 1) v += __shfl_xor_sync(0xffffffffu, v, off);
    return v;
}
static __device__ __forceinline__ float wmax(float v) {
    #pragma unroll
    for (int off = 16; off; off >>= 1) v = fmaxf(v, __shfl_xor_sync(0xffffffffu, v, off));
    return v;
}

// batch-scoped barrier: all G_ CTAs of this batch arrive, then proceed.
// All 128 CTAs are co-resident (grid 128 <= 148 SMs, 1 CTA/SM), so spinning is safe.
static __device__ __forceinline__ void batch_bar(unsigned* cnt) {
    __threadfence();
    __syncthreads();
    if (threadIdx.x == 0) {
        atomicAdd(cnt, 1u);
        while (*(volatile unsigned*)cnt < G_) __nanosleep(32);
        __threadfence();
    }
    __syncthreads();
}

// ===========================================================================
__global__ void __launch_bounds__(1024, 1) fused_attn(
    const float* __restrict__ x1, const float* __restrict__ x2,
    const float* __restrict__ W1, const float* __restrict__ bb1,
    const float* __restrict__ U1, const float* __restrict__ W2,
    const float* __restrict__ bb2, const float* __restrict__ U2,
    float* __restrict__ out)
{
    const int b    = blockIdx.x >> 2;
    const int g    = blockIdx.x & 3;
    const int tid  = threadIdx.x;
    const int lane = tid & 31;
    const int w    = tid >> 5;
    const int t0   = g * ROWS;
    const int rbase = w * RPW;

    __shared__ float4 sred[2][NW][32];   // warp-reduction scratch (32 KB)
    __shared__ float  vsh[2][E_];        // s (phase B) then c (phase C)
    __shared__ float  tsh[2][ROWS];      // d -> et -> softmax weights
    __shared__ float2 stsh[2][16];       // per-warp softmax stats (16 warps/tensor)
    __shared__ float  s_m[2], s_iz[2];

    const float4* p1 = (const float4*)(x1 + ((size_t)b * T_ + t0) * E_);
    const float4* p2 = (const float4*)(x2 + ((size_t)b * T_ + t0) * E_);

    // ======== Phase A: PURE streaming column sums (no shuffles) ============
    // Load->FADD only: loads pipeline freely, DRAM pass runs at high MLP.
    {
        float4 s1a = {0,0,0,0}, s2a = {0,0,0,0};
        #pragma unroll 4
        for (int rr = 0; rr < RPW; rr++) {
            int row = rbase + rr;
            float4 v1 = __ldg(p1 + row * 32 + lane);
            float4 v2 = __ldg(p2 + row * 32 + lane);
            s1a.x += v1.x; s1a.y += v1.y; s1a.z += v1.z; s1a.w += v1.w;
            s2a.x += v2.x; s2a.y += v2.y; s2a.z += v2.z; s2a.w += v2.w;
        }
        sred[0][w][lane] = s1a;
        sred[1][w][lane] = s2a;
        __syncthreads();
        if (tid < 64) {
            int ti = tid >> 5;
            float4 s = sred[ti][0][lane];
            #pragma unroll
            for (int k = 1; k < NW; k++) {
                float4 v = sred[ti][k][lane];
                s.x += v.x; s.y += v.y; s.z += v.z; s.w += v.w;
            }
            ((float4*)&g_s_part[ti][b][g][0])[lane] = s;
        }
    }
    batch_bar(&g_bar[b][0]);

    // full column sums into smem
    if (tid < 256) {
        int ti = tid >> 7, e = tid & 127;
        float acc = 0.f;
        #pragma unroll
        for (int gg = 0; gg < G_; gg++) acc += g_s_part[ti][b][gg][e];
        vsh[ti][e] = acc;
    }
    __syncthreads();

    // ======== Phase B: c partials + row dots d (merged 4-way reduction) ====
    {
        float4 s1l = ((const float4*)vsh[0])[lane];
        float4 s2l = ((const float4*)vsh[1])[lane];
        float4 w1l = ((const float4*)W1)[lane];
        float4 w2l = ((const float4*)W2)[lane];
        float4 c1a = {0,0,0,0}, c2a = {0,0,0,0};
        #pragma unroll 2
        for (int rr = 0; rr < RPW; rr++) {
            int row = rbase + rr;
            float4 v1 = __ldg(p1 + row * 32 + lane);
            float4 v2 = __ldg(p2 + row * 32 + lane);
            float q0 = dot4(v1, s2l);   // a1 = x1 . s2
            float q1 = dot4(v2, s1l);   // a2 = x2 . s1
            float q2 = dot4(v1, w1l);   // d1 = x1 . W1
            float q3 = dot4(v2, w2l);   // d2 = x2 . W2
            // merged butterfly: 2 shared rounds on 4 values
            q0 += __shfl_xor_sync(0xffffffffu, q0, 16);
            q1 += __shfl_xor_sync(0xffffffffu, q1, 16);
            q2 += __shfl_xor_sync(0xffffffffu, q2, 16);
            q3 += __shfl_xor_sync(0xffffffffu, q3, 16);
            q0 += __shfl_xor_sync(0xffffffffu, q0, 8);
            q1 += __shfl_xor_sync(0xffffffffu, q1, 8);
            q2 += __shfl_xor_sync(0xffffffffu, q2, 8);
            q3 += __shfl_xor_sync(0xffffffffu, q3, 8);
            // each q_i now summed over lanes sharing (lane&7); lanes 0..7
            // of each value's class cover all 8 residues. Select by group.
            float q = (lane < 8) ? q0 : (lane < 16) ? q1 : (lane < 24) ? q2 : q3;
            q += __shfl_xor_sync(0xffffffffu, q, 4);
            q += __shfl_xor_sync(0xffffffffu, q, 2);
            q += __shfl_xor_sync(0xffffffffu, q, 1);
            // lanes 0-7: a1 total; 8-15: a2; 16-23: d1; 24-31: d2
            float a1 = __shfl_sync(0xffffffffu, q, 0);
            float a2 = __shfl_sync(0xffffffffu, q, 8);
            if (lane == 16) tsh[0][row] = q;   // d1
            if (lane == 24) tsh[1][row] = q;   // d2
            c1a.x = fmaf(a1, v2.x, c1a.x); c1a.y = fmaf(a1, v2.y, c1a.y);
            c1a.z = fmaf(a1, v2.z, c1a.z); c1a.w = fmaf(a1, v2.w, c1a.w);
            c2a.x = fmaf(a2, v1.x, c2a.x); c2a.y = fmaf(a2, v1.y, c2a.y);
            c2a.z = fmaf(a2, v1.z, c2a.z); c2a.w = fmaf(a2, v1.w, c2a.w);
        }
        sred[0][w][lane] = c1a;
        sred[1][w][lane] = c2a;
        __syncthreads();
        if (tid < 64) {
            int ti = tid >> 5;
            float4 s = sred[ti][0][lane];
            #pragma unroll
            for (int k = 1; k < NW; k++) {
                float4 v = sred[ti][k][lane];
                s.x += v.x; s.y += v.y; s.z += v.z; s.w += v.w;
            }
            ((float4*)&g_c_part[ti][b][g][0])[lane] = s;
        }
    }
    batch_bar(&g_bar[b][1]);

    // full c (scaled) into smem
    if (tid < 256) {
        int ti = tid >> 7, e = tid & 127;
        float acc = 0.f;
        #pragma unroll
        for (int gg = 0; gg < G_; gg++) acc += g_c_part[ti][b][gg][e];
        vsh[ti][e] = acc * INV_T;
    }
    __syncthreads();

    // ======== Phase C: logits + per-CTA softmax stats ======================
    {
        int p    = tid >> 9;
        int tloc = tid & 511;
        int wp   = tloc >> 5;              // warp index within tensor (0..15)
        const float* U    = p ? U2  : U1;
        const float* bias = p ? bb2 : bb1;
        int t = t0 + tloc;
        float acc = 0.f;
        #pragma unroll 8
        for (int e = 0; e < E_; e++)
            acc = fmaf(vsh[p][e], __ldg(&U[e * T_ + t]), acc);
        float et = acc + tsh[p][tloc] + __ldg(&bias[t]);
        __syncthreads();                   // tsh read (d) before overwrite
        tsh[p][tloc] = et;
        float m = wmax(et);
        float z = wsum(__expf(et - m));
        if (lane == 0) stsh[p][wp] = make_float2(m, z);
    }
    __syncthreads();
    if (tid < 2) {
        float m = -3.4e38f;
        #pragma unroll
        for (int i = 0; i < 16; i++) m = fmaxf(m, stsh[tid][i].x);
        float z = 0.f;
        #pragma unroll
        for (int i = 0; i < 16; i++) {
            float2 st = stsh[tid][i];
            z += st.y * __expf(st.x - m);
        }
        g_stats[tid][b][g] = make_float2(m, z);
    }
    batch_bar(&g_bar[b][2]);
    if (tid < 2) {
        float m = -3.4e38f;
        #pragma unroll
        for (int gg = 0; gg < G_; gg++) m = fmaxf(m, g_stats[tid][b][gg].x);
        float z = 0.f;
        #pragma unroll
        for (int gg = 0; gg < G_; gg++) {
            float2 st = g_stats[tid][b][gg];
            z += st.y * __expf(st.x - m);
        }
        s_m[tid]  = m;
        s_iz[tid] = 1.0f / z;
    }
    __syncthreads();

    // ======== Phase D: softmax weights + weighted sums (shuffle-free) ======
    {
        int ti = tid >> 9, rr = tid & 511;     // 1024 threads = 2*ROWS exactly
        tsh[ti][rr] = __expf(tsh[ti][rr] - s_m[ti]) * s_iz[ti];
    }
    __syncthreads();
    {
        float4 o1a = {0,0,0,0}, o2a = {0,0,0,0};
        #pragma unroll 2
        for (int rr = 0; rr < RPW; rr++) {
            int row = rbase + rr;
            float wt1 = tsh[0][row];
            float wt2 = tsh[1][row];
            float4 v1 = __ldg(p1 + row * 32 + lane);
            float4 v2 = __ldg(p2 + row * 32 + lane);
            o1a.x = fmaf(wt1, v1.x, o1a.x); o1a.y = fmaf(wt1, v1.y, o1a.y);
            o1a.z = fmaf(wt1, v1.z, o1a.z); o1a.w = fmaf(wt1, v1.w, o1a.w);
            o2a.x = fmaf(wt2, v2.x, o2a.x); o2a.y = fmaf(wt2, v2.y, o2a.y);
            o2a.z = fmaf(wt2, v2.z, o2a.z); o2a.w = fmaf(wt2, v2.w, o2a.w);
        }
        sred[0][w][lane] = o1a;
        sred[1][w][lane] = o2a;
        __syncthreads();
        if (tid < 64) {
            int ti = tid >> 5;
            float4 s = sred[ti][0][lane];
            #pragma unroll
            for (int k = 1; k < NW; k++) {
                float4 v = sred[ti][k][lane];
                s.x += v.x; s.y += v.y; s.z += v.z; s.w += v.w;
            }
            ((float4*)&g_o_part[ti][b][g][0])[lane] = s;
        }
    }
    batch_bar(&g_bar[b][3]);

    // ---------------- output: CTA g writes its 64 of 256 values ------------
    if (tid < 64) {
        int idx = g * 64 + tid;
        int ti = idx >> 7, e = idx & 127;
        float acc = 0.f;
        #pragma unroll
        for (int gg = 0; gg < G_; gg++) acc += g_o_part[ti][b][gg][e];
        out[b * 256 + idx] = acc;
    }

    // ---------------- cleanup: last CTA of the batch resets counters -------
    __syncthreads();
    if (tid == 0) {
        unsigned old = atomicAdd(&g_bar[b][4], 1u);
        if (old == G_ - 1) {
            #pragma unroll
            for (int i = 0; i < 5; i++) g_bar[b][i] = 0u;
        }
    }
}

// ===========================================================================
extern "C" void kernel_launch(void* const* d_in, const int* in_sizes, int n_in,
                              void* d_out, int out_size)
{
    const float* x1 = (const float*)d_in[0];
    const float* x2 = (const float*)d_in[1];
    const float* W1 = (const float*)d_in[2];
    const float* b1 = (const float*)d_in[3];
    const float* U1 = (const float*)d_in[4];
    const float* W2 = (const float*)d_in[5];
    const float* b2 = (const float*)d_in[6];
    const float* U2 = (const float*)d_in[7];
    float* out = (float*)d_out;

    fused_attn<<<B_ * G_, 1024>>>(x1, x2, W1, b1, U1, W2, b2, U2, out);
}